// round 6
// baseline (speedup 1.0000x reference)
#include <cuda_runtime.h>

// Pooled attention embedding bag, GB300 (sm_103a).
//   B=8192 bags, L<=64/bag (via offsets), D=64, ATT=64, K=4.
//   out[b,k,:] = sum_i softmax_i( tanh(E_i @ Wp^T + b) @ att_h )[k] * E_i
//
// R6: 2 bags/CTA (64 item slots each), 256 thr, ~54.6KB smem, 4 CTAs/SM.
//  * ET[d][item] transposed store, PADN=132 (== 4 mod 8): gather STS is
//    fully bank-conflict-free (16 consecutive banks per half-warp, halves
//    16 banks apart); GEMM reads 8 consecutive items per thread via two
//    LDS.128 -> 4 wavefronts/d/warp (W:2 + E:2).
//  * fma.rn.f32x2 item-pair packed accumulation (16 FFMA2 per d per thread).
//  * Second GEMM (H @ att_h) fused in epilogue; compress-split 16-lane
//    shuffle reduction (8 SHFL per item-pair).
//  * Pooling: float4 ET loads + one broadcast double2 of k-packed weights
//    per item; f32x2 accumulation; coalesced strided stores.

namespace {
constexpr int Dm    = 64;
constexpr int ATTm  = 64;
constexpr int KN    = 4;
constexpr int NB    = 2;               // bags per CTA
constexpr int MAXI  = 64;              // item slots per bag
constexpr int NITEM = NB * MAXI;       // 128
constexpr int PADW  = 68;              // W row pad (floats)
constexpr int PADN  = 132;             // ET row pad; 132 % 8 == 4 (see above)
constexpr int NT    = 256;
constexpr int SMEM_FLOATS = 64*PADW    // Wt [d][a]
                          + 64*PADN    // ET [d][item]
                          + NITEM*KN   // At [item][k]
                          + KN*PADW    // AhT[k][a]
                          + ATTm       // Pb
                          + 8;         // Red [bag][k] = 1/sum
}

__device__ int   g_idx_is64;
__device__ float g_Wt[64 * 64];        // g_Wt[d*64+a] = projw[a*64+d]

using ull = unsigned long long;

__device__ __forceinline__ float tanh_fast(float x) {
    float y; asm("tanh.approx.f32 %0, %1;" : "=f"(y) : "f"(x)); return y;
}
__device__ __forceinline__ void ffma2(ull& d, ull a, ull b) {
    asm("fma.rn.f32x2 %0, %1, %2, %0;" : "+l"(d) : "l"(a), "l"(b));
}
__device__ __forceinline__ ull bcast2(float x) {
    ull r; asm("mov.b64 %0, {%1, %1};" : "=l"(r) : "f"(x)); return r;
}
__device__ __forceinline__ void unpack2(float& lo, float& hi, ull v) {
    asm("mov.b64 {%0, %1}, %2;" : "=f"(lo), "=f"(hi) : "l"(v));
}
__device__ __forceinline__ long long ld_idx(const void* p, long long i, int is64) {
    return is64 ? ((const long long*)p)[i] : (long long)((const int*)p)[i];
}

extern "C" __global__ void prep_kernel(const float* __restrict__ projw,
                                       const void* __restrict__ input_,
                                       const void* __restrict__ offsets,
                                       long long nnz, int nseg, long long vocab) {
    int t = threadIdx.x;
    for (int p = t; p < 64 * 64; p += 256) {
        int a = p >> 6, d = p & 63;
        g_Wt[d * 64 + a] = projw[p];
    }
    if (t == 0) {
        bool ok = true;
        const long long* o64 = (const long long*)offsets;
        int no = nseg < 4 ? nseg : 4;
        long long prev = -1;
        for (int i = 0; i < no; ++i) {
            long long v = o64[i];
            if (v < 0 || v > nnz || v < prev) ok = false;
            prev = v;
        }
        const long long* in64 = (const long long*)input_;
        long long ni = nnz < 8 ? nnz : 8;
        for (long long i = 0; i < ni; ++i) {
            long long v = in64[i];
            if (v < 0 || v >= vocab) ok = false;
        }
        g_idx_is64 = ok ? 1 : 0;
    }
}

extern "C" __global__ void __launch_bounds__(NT, 4)
pooled_att_kernel(const void*  __restrict__ input_,
                  const void*  __restrict__ offsets,
                  const float* __restrict__ emb,
                  const float* __restrict__ projb,
                  const float* __restrict__ atth,
                  float*       __restrict__ out,
                  int nseg, long long nnz)
{
    extern __shared__ float sm[];
    float* Wt  = sm;                    // [64][PADW]
    float* ET  = Wt  + 64*PADW;         // [64][PADN]  ET[d*PADN+item]
    float* At  = ET  + 64*PADN;         // [NITEM][KN]
    float* AhT = At  + NITEM*KN;        // [KN][PADW]
    float* Pb  = AhT + KN*PADW;         // [64]
    float* Red = Pb  + ATTm;            // [NB][KN]

    __shared__ long long s_start[NB];
    __shared__ int       s_cnt[NB];

    const int tid  = threadIdx.x;
    const int is64 = g_idx_is64;

    if (tid < NB) {
        int bg = blockIdx.x * NB + tid;
        long long st = 0, en = 0;
        if (bg < nseg) {
            st = ld_idx(offsets, bg, is64);
            en = (bg + 1 < nseg) ? ld_idx(offsets, bg + 1, is64) : nnz;
        }
        long long c = en - st;
        if (c < 0) c = 0;
        if (c > MAXI) c = MAXI;
        s_cnt[tid]   = (int)c;
        s_start[tid] = st;
    }
    // stage Wt (coalesced float4, conflict-free), AhT, Pb
    for (int q = tid; q < 64 * 16; q += NT) {
        int d = q >> 4, c4 = q & 15;
        *reinterpret_cast<float4*>(Wt + d * PADW + c4 * 4) =
            reinterpret_cast<const float4*>(g_Wt)[q];
    }
    if (tid < ATTm * KN) {
        int a = tid >> 2, k = tid & 3;
        AhT[k * PADW + a] = atth[tid];
    }
    if (tid < ATTm) Pb[tid] = projb[tid];
    __syncthreads();                    // s_cnt ready

    // ---- gather: warp = 16 items x 2 d-quarters; conflict-free STS ----
    {
        const int il   = tid & 15;          // item within group of 16
        const int qh   = (tid >> 4) & 1;    // quarter parity
        const int g    = tid >> 5;          // warp = item group (8 groups)
        const int item = g * 16 + il;
        const int b    = item >> 6;
        const int it   = item & 63;
        const bool valid = it < s_cnt[b];
        long long idx = 0;
        if (valid) idx = ld_idx(input_, s_start[b] + it, is64);
        const float4* src = reinterpret_cast<const float4*>(emb + idx * (long long)Dm);
        float* dst = ET + item;
        #pragma unroll
        for (int q2 = 0; q2 < 8; ++q2) {
            const int quarter = q2 * 2 + qh;
            float4 v = make_float4(0.f, 0.f, 0.f, 0.f);
            if (valid) v = src[quarter];
            const int d0 = quarter * 4;
            dst[(d0 + 0) * PADN] = v.x;
            dst[(d0 + 1) * PADN] = v.y;
            dst[(d0 + 2) * PADN] = v.z;
            dst[(d0 + 3) * PADN] = v.w;
        }
    }
    __syncthreads();                    // ET + Wt ready

    // ---- GEMM: thread = (a-quad aq, 8 consecutive items 8*tg..8*tg+7) ----
    const int aq = tid & 15;
    const int tg = tid >> 4;            // 0..15

    ull acc[4][4];                      // [a][pair r]; pair r = items 8tg+2r..+1
    #pragma unroll
    for (int a = 0; a < 4; ++a)
        #pragma unroll
        for (int r = 0; r < 4; ++r) acc[a][r] = 0ull;

    {
        const float* wrow = Wt + 4 * aq;
        const float* erow = ET + 8 * tg;
        #pragma unroll 8
        for (int d = 0; d < 64; ++d) {
            float4 wq = *reinterpret_cast<const float4*>(wrow + d * PADW);
            ull w0 = bcast2(wq.x), w1 = bcast2(wq.y);
            ull w2 = bcast2(wq.z), w3 = bcast2(wq.w);
            double2 eA = *reinterpret_cast<const double2*>(erow + d * PADN);
            double2 eB = *reinterpret_cast<const double2*>(erow + d * PADN + 4);
            const ull e0 = __double_as_longlong(eA.x);
            const ull e1 = __double_as_longlong(eA.y);
            const ull e2 = __double_as_longlong(eB.x);
            const ull e3 = __double_as_longlong(eB.y);
            ffma2(acc[0][0], w0, e0); ffma2(acc[1][0], w1, e0);
            ffma2(acc[2][0], w2, e0); ffma2(acc[3][0], w3, e0);
            ffma2(acc[0][1], w0, e1); ffma2(acc[1][1], w1, e1);
            ffma2(acc[2][1], w2, e1); ffma2(acc[3][1], w3, e1);
            ffma2(acc[0][2], w0, e2); ffma2(acc[1][2], w1, e2);
            ffma2(acc[2][2], w2, e2); ffma2(acc[3][2], w3, e2);
            ffma2(acc[0][3], w0, e3); ffma2(acc[1][3], w1, e3);
            ffma2(acc[2][3], w2, e3); ffma2(acc[3][3], w3, e3);
        }
    }

    // ---- epilogue: tanh + (H @ att_h) + compress-split 16-lane reduction ----
    {
        const int a0 = 4 * aq;
        const float pb0 = Pb[a0], pb1 = Pb[a0+1], pb2 = Pb[a0+2], pb3 = Pb[a0+3];
        const float4 ah0 = *reinterpret_cast<const float4*>(AhT + 0 * PADW + a0);
        const float4 ah1 = *reinterpret_cast<const float4*>(AhT + 1 * PADW + a0);
        const float4 ah2 = *reinterpret_cast<const float4*>(AhT + 2 * PADW + a0);
        const float4 ah3 = *reinterpret_cast<const float4*>(AhT + 3 * PADW + a0);
        const bool u8 = (aq & 8) != 0, u4 = (aq & 4) != 0, u2 = (aq & 2) != 0;
        const int j  = (u8 ? 4 : 0) | (u4 ? 2 : 0) | (u2 ? 1 : 0);
        const int kk = j & 3, hh = j >> 2;

        #pragma unroll
        for (int r = 0; r < 4; ++r) {
            float lo0, hi0, lo1, hi1, lo2, hi2, lo3, hi3;
            unpack2(lo0, hi0, acc[0][r]); unpack2(lo1, hi1, acc[1][r]);
            unpack2(lo2, hi2, acc[2][r]); unpack2(lo3, hi3, acc[3][r]);
            float hl0 = tanh_fast(lo0 + pb0), hg0 = tanh_fast(hi0 + pb0);
            float hl1 = tanh_fast(lo1 + pb1), hg1 = tanh_fast(hi1 + pb1);
            float hl2 = tanh_fast(lo2 + pb2), hg2 = tanh_fast(hi2 + pb2);
            float hl3 = tanh_fast(lo3 + pb3), hg3 = tanh_fast(hi3 + pb3);

            float v[8];
            v[0] = hl0*ah0.x + hl1*ah0.y + hl2*ah0.z + hl3*ah0.w;
            v[1] = hl0*ah1.x + hl1*ah1.y + hl2*ah1.z + hl3*ah1.w;
            v[2] = hl0*ah2.x + hl1*ah2.y + hl2*ah2.z + hl3*ah2.w;
            v[3] = hl0*ah3.x + hl1*ah3.y + hl2*ah3.z + hl3*ah3.w;
            v[4] = hg0*ah0.x + hg1*ah0.y + hg2*ah0.z + hg3*ah0.w;
            v[5] = hg0*ah1.x + hg1*ah1.y + hg2*ah1.z + hg3*ah1.w;
            v[6] = hg0*ah2.x + hg1*ah2.y + hg2*ah2.z + hg3*ah2.w;
            v[7] = hg0*ah3.x + hg1*ah3.y + hg2*ah3.z + hg3*ah3.w;

            float s0, s1, s2, s3;
            {
                float t0 = u8 ? v[0] : v[4];
                float t1 = u8 ? v[1] : v[5];
                float t2 = u8 ? v[2] : v[6];
                float t3 = u8 ? v[3] : v[7];
                s0 = (u8 ? v[4] : v[0]) + __shfl_xor_sync(0xffffffffu, t0, 8);
                s1 = (u8 ? v[5] : v[1]) + __shfl_xor_sync(0xffffffffu, t1, 8);
                s2 = (u8 ? v[6] : v[2]) + __shfl_xor_sync(0xffffffffu, t2, 8);
                s3 = (u8 ? v[7] : v[3]) + __shfl_xor_sync(0xffffffffu, t3, 8);
            }
            float q0, q1;
            {
                float t0 = u4 ? s0 : s2;
                float t1 = u4 ? s1 : s3;
                q0 = (u4 ? s2 : s0) + __shfl_xor_sync(0xffffffffu, t0, 4);
                q1 = (u4 ? s3 : s1) + __shfl_xor_sync(0xffffffffu, t1, 4);
            }
            float t = u2 ? q0 : q1;
            float w = (u2 ? q1 : q0) + __shfl_xor_sync(0xffffffffu, t, 2);
            w += __shfl_xor_sync(0xffffffffu, w, 1);

            if ((aq & 1) == 0)
                At[(8 * tg + 2 * r + hh) * KN + kk] = w;
        }
    }
    __syncthreads();                    // At ready

    // ---- ragged softmax: warp j -> bag j ----
    {
        const int w    = tid >> 5;
        const int lane = tid & 31;
        if (w < NB) {
            const int k = lane & 3, grp = lane >> 2;
            const int c = s_cnt[w];
            float* ab = At + (w * MAXI) * KN + k;
            float m = -1e30f;
            #pragma unroll
            for (int it = 0; it < 8; ++it) {
                int i = grp + (it << 3);
                if (i < c) m = fmaxf(m, ab[i * KN]);
            }
            #pragma unroll
            for (int off = 4; off <= 16; off <<= 1)
                m = fmaxf(m, __shfl_xor_sync(0xffffffffu, m, off));
            float s = 0.f;
            #pragma unroll
            for (int it = 0; it < 8; ++it) {
                int i = grp + (it << 3);
                if (i < c) {
                    float e = __expf(ab[i * KN] - m);
                    ab[i * KN] = e;
                    s += e;
                }
            }
            #pragma unroll
            for (int off = 4; off <= 16; off <<= 1)
                s += __shfl_xor_sync(0xffffffffu, s, off);
            if (grp == 0) Red[w * KN + k] = (s > 0.f) ? 1.0f / s : 0.f;
        }
    }
    __syncthreads();                    // weights + Red ready

    // ---- pooling: 128 threads = 2 bags x 64 d; vectorized ----
    if (tid < 128) {
        const int b  = tid >> 6;
        const int d  = tid & 63;
        const int bg = blockIdx.x * NB + b;
        if (bg < nseg) {
            const int c = s_cnt[b];
            const float* ep = ET + d * PADN + b * MAXI;
            const float* ap = At + (b * MAXI) * KN;
            ull a01 = 0ull, a23 = 0ull;
            int i = 0;
            for (; i + 4 <= c; i += 4) {
                float4 e4 = *reinterpret_cast<const float4*>(ep + i);
                double2 wv0 = *reinterpret_cast<const double2*>(ap + (i + 0) * KN);
                double2 wv1 = *reinterpret_cast<const double2*>(ap + (i + 1) * KN);
                double2 wv2 = *reinterpret_cast<const double2*>(ap + (i + 2) * KN);
                double2 wv3 = *reinterpret_cast<const double2*>(ap + (i + 3) * KN);
                ull ex = bcast2(e4.x), ey = bcast2(e4.y);
                ull ez = bcast2(e4.z), ew = bcast2(e4.w);
                ffma2(a01, ex, __double_as_longlong(wv0.x));
                ffma2(a23, ex, __double_as_longlong(wv0.y));
                ffma2(a01, ey, __double_as_longlong(wv1.x));
                ffma2(a23, ey, __double_as_longlong(wv1.y));
                ffma2(a01, ez, __double_as_longlong(wv2.x));
                ffma2(a23, ez, __double_as_longlong(wv2.y));
                ffma2(a01, ew, __double_as_longlong(wv3.x));
                ffma2(a23, ew, __double_as_longlong(wv3.y));
            }
            for (; i < c; ++i) {
                double2 wv = *reinterpret_cast<const double2*>(ap + i * KN);
                ull ev = bcast2(ep[i]);
                ffma2(a01, ev, __double_as_longlong(wv.x));
                ffma2(a23, ev, __double_as_longlong(wv.y));
            }
            float r0, r1, r2, r3;
            unpack2(r0, r1, a01);
            unpack2(r2, r3, a23);
            float* op = out + (size_t)bg * (KN * Dm) + d;
            op[0]      = r0 * Red[b * KN + 0];
            op[Dm]     = r1 * Red[b * KN + 1];
            op[2 * Dm] = r2 * Red[b * KN + 2];
            op[3 * Dm] = r3 * Red[b * KN + 3];
        }
    }
}

extern "C" void kernel_launch(void* const* d_in, const int* in_sizes, int n_in,
                              void* d_out, int out_size) {
    const void*  input_  = d_in[0];
    const void*  offsets = d_in[1];
    const float* emb     = (const float*)d_in[2];
    const float* projw   = (const float*)d_in[3];
    const float* projb   = (const float*)d_in[4];
    const float* atth    = (const float*)d_in[5];
    float* out = (float*)d_out;

    const int       nseg  = in_sizes[1];
    const long long nnz   = in_sizes[0];
    const long long vocab = (long long)in_sizes[2] / Dm;

    prep_kernel<<<1, 256>>>(projw, input_, offsets, nnz, nseg, vocab);

    const size_t smem = SMEM_FLOATS * sizeof(float);  // ~54.6 KB
    cudaFuncSetAttribute(pooled_att_kernel,
                         cudaFuncAttributeMaxDynamicSharedMemorySize, (int)smem);
    const int grid = (nseg + NB - 1) / NB;
    pooled_att_kernel<<<grid, NT, smem>>>(input_, offsets, emb, projb,
                                          atth, out, nseg, nnz);
}

// round 8
// speedup vs baseline: 1.5279x; 1.5279x over previous
#include <cuda_runtime.h>
#include <cuda_bf16.h>

// Pooled attention embedding bag, GB300 (sm_103) — legacy HMMA tensor-core
// version (mma.sync.m16n8k16 bf16 — no sm_103a-only features).
//   B=8192 bags, L<=64/bag (via offsets), D=64, ATT=64, K=4.
//   out[b,k,:] = sum_i softmax_i( tanh(E_i @ Wp^T + b) @ att_h )[k] * E_i
//
// Per CTA: 2 bags = 128 item rows. 8 warps; warp w computes rows 16w..16w+15
// of H = E(bf16) @ projw(bf16)^T with 4 k-steps x 8 n-tiles of
// mma.m16n8k16.row.col.f32.bf16.bf16.f32, operands via ldmatrix from smem
// (72-element rows: consecutive rows 4 banks apart -> conflict-free).
// Epilogue in registers: tanh+bias, x att_h, quad-shuffle reduce -> At.
// Warp softmax per bag; pooling re-reads E fp32 from global (L2-resident).

namespace {
constexpr int Dm = 64, KN = 4, NB = 2, MAXI = 64, NT = 256;
constexpr int LDA = 72;          // bf16 row stride for A/B tiles (144B)
}

__device__ int      g_idx_is64;
__device__ unsigned g_Wb[2048];  // projw as bf16x2, row-major [64][64]

using ull = unsigned long long;

__device__ __forceinline__ float tanh_fast(float x) {
    float y; asm("tanh.approx.f32 %0, %1;" : "=f"(y) : "f"(x)); return y;
}
__device__ __forceinline__ void ffma2(ull& d, ull a, ull b) {
    asm("fma.rn.f32x2 %0, %1, %2, %0;" : "+l"(d) : "l"(a), "l"(b));
}
__device__ __forceinline__ ull bcast2(float x) {
    ull r; asm("mov.b64 %0, {%1, %1};" : "=l"(r) : "f"(x)); return r;
}
__device__ __forceinline__ void unpack2(float& lo, float& hi, ull v) {
    asm("mov.b64 {%0, %1}, %2;" : "=f"(lo), "=f"(hi) : "l"(v));
}
__device__ __forceinline__ long long ld_idx(const void* p, long long i, int is64) {
    return is64 ? ((const long long*)p)[i] : (long long)((const int*)p)[i];
}
__device__ __forceinline__ unsigned smem_u32(const void* p) {
    unsigned a;
    asm("{ .reg .u64 t; cvta.to.shared.u64 t, %1; cvt.u32.u64 %0, t; }"
        : "=r"(a) : "l"(p));
    return a;
}
__device__ __forceinline__ void ldsm_x4(unsigned& r0, unsigned& r1,
                                        unsigned& r2, unsigned& r3, unsigned addr) {
    asm volatile("ldmatrix.sync.aligned.m8n8.x4.shared.b16 {%0,%1,%2,%3}, [%4];"
                 : "=r"(r0), "=r"(r1), "=r"(r2), "=r"(r3) : "r"(addr));
}
__device__ __forceinline__ void ldsm_x2(unsigned& r0, unsigned& r1, unsigned addr) {
    asm volatile("ldmatrix.sync.aligned.m8n8.x2.shared.b16 {%0,%1}, [%2];"
                 : "=r"(r0), "=r"(r1) : "r"(addr));
}
__device__ __forceinline__ void mma16816(float* c, unsigned a0, unsigned a1,
                                         unsigned a2, unsigned a3,
                                         unsigned b0, unsigned b1) {
    asm volatile(
        "mma.sync.aligned.m16n8k16.row.col.f32.bf16.bf16.f32 "
        "{%0,%1,%2,%3}, {%4,%5,%6,%7}, {%8,%9}, {%0,%1,%2,%3};"
        : "+f"(c[0]), "+f"(c[1]), "+f"(c[2]), "+f"(c[3])
        : "r"(a0), "r"(a1), "r"(a2), "r"(a3), "r"(b0), "r"(b1));
}

// prep: projw fp32 -> bf16 (row-major, no transpose needed); idx dtype detect.
extern "C" __global__ void prep_kernel(const float* __restrict__ projw,
                                       const void* __restrict__ input_,
                                       const void* __restrict__ offsets,
                                       long long nnz, int nseg, long long vocab) {
    int t = threadIdx.x;
    for (int q = t; q < 2048; q += 256) {
        __nv_bfloat162 v = __floats2bfloat162_rn(projw[2 * q], projw[2 * q + 1]);
        g_Wb[q] = *reinterpret_cast<unsigned*>(&v);
    }
    if (t == 0) {
        bool ok = true;
        const long long* o64 = (const long long*)offsets;
        int no = nseg < 4 ? nseg : 4;
        long long prev = -1;
        for (int i = 0; i < no; ++i) {
            long long v = o64[i];
            if (v < 0 || v > nnz || v < prev) ok = false;
            prev = v;
        }
        const long long* in64 = (const long long*)input_;
        long long ni = nnz < 8 ? nnz : 8;
        for (long long i = 0; i < ni; ++i) {
            long long v = in64[i];
            if (v < 0 || v >= vocab) ok = false;
        }
        g_idx_is64 = ok ? 1 : 0;
    }
}

extern "C" __global__ void __launch_bounds__(NT, 4)
pooled_att_hmma(const void*  __restrict__ input_,
                const void*  __restrict__ offsets,
                const float* __restrict__ emb,
                const float* __restrict__ projb,
                const float* __restrict__ atth,
                float*       __restrict__ out,
                int nseg, long long nnz)
{
    __shared__ __align__(16) __nv_bfloat16 As[128 * LDA];  // E tile (bf16)
    __shared__ __align__(16) __nv_bfloat16 Bs[64 * LDA];   // projw tile (bf16)
    __shared__ float     At[128 * KN];
    __shared__ float     Ah[64 * KN];     // atth row-major [att][K]
    __shared__ float     Pbs[64];
    __shared__ float     red[NB * KN];
    __shared__ long long s_idx[128];
    __shared__ long long s_start[NB];
    __shared__ int       s_cnt[NB];

    const int tid = threadIdx.x;
    const int w   = tid >> 5;
    const int l   = tid & 31;
    const int is64 = g_idx_is64;

    if (tid < NB) {
        int bg = blockIdx.x * NB + tid;
        long long st = 0, en = 0;
        if (bg < nseg) {
            st = ld_idx(offsets, bg, is64);
            en = (bg + 1 < nseg) ? ld_idx(offsets, bg + 1, is64) : nnz;
        }
        long long c = en - st;
        if (c < 0) c = 0;
        if (c > MAXI) c = MAXI;
        s_cnt[tid] = (int)c;
        s_start[tid] = st;
    }
    // stage B (bf16, padded rows), Ah, Pb
    for (int q = tid; q < 2048; q += NT) {
        int row = q >> 5, cp = q & 31;
        *reinterpret_cast<unsigned*>(Bs + row * LDA + cp * 2) = g_Wb[q];
    }
    if (tid < 64) Pbs[tid] = projb[tid];
    if (tid < 256) Ah[tid] = atth[tid];
    __syncthreads();                       // s_cnt ready

    // ---- gather: 2 threads per item row; fp32 -> bf16 into As ----
    {
        const int row = tid >> 1, half = tid & 1;
        const int b = row >> 6, it = row & 63;
        const bool valid = it < s_cnt[b];
        long long idx = 0;
        if (valid) idx = ld_idx(input_, s_start[b] + it, is64);
        if (half == 0) s_idx[row] = idx;
        const float4* src =
            reinterpret_cast<const float4*>(emb + idx * (long long)Dm + half * 32);
        __nv_bfloat16* dst = As + row * LDA + half * 32;
        #pragma unroll
        for (int c = 0; c < 8; ++c) {
            float4 v = make_float4(0.f, 0.f, 0.f, 0.f);
            if (valid) v = src[c];
            __nv_bfloat162 lo = __floats2bfloat162_rn(v.x, v.y);
            __nv_bfloat162 hi = __floats2bfloat162_rn(v.z, v.w);
            ull pv = ((ull)(*reinterpret_cast<unsigned*>(&hi)) << 32)
                   |  (ull)(*reinterpret_cast<unsigned*>(&lo));
            *reinterpret_cast<ull*>(dst + c * 4) = pv;
        }
    }
    __syncthreads();                       // As + Bs ready

    // ---- HMMA GEMM: warp w -> rows 16w..16w+15; 8 n-tiles, 4 k-steps ----
    float acc[8][4];
    #pragma unroll
    for (int n = 0; n < 8; ++n)
        #pragma unroll
        for (int j = 0; j < 4; ++j) acc[n][j] = 0.f;

    #pragma unroll
    for (int ks = 0; ks < 4; ++ks) {
        unsigned a0, a1, a2, a3;
        {
            const __nv_bfloat16* ap =
                As + (16 * w + (l & 15)) * LDA + ks * 16 + (l >> 4) * 8;
            ldsm_x4(a0, a1, a2, a3, smem_u32(ap));
        }
        #pragma unroll
        for (int n = 0; n < 8; ++n) {
            unsigned b0, b1;
            const __nv_bfloat16* bp =
                Bs + (8 * n + (l & 7)) * LDA + ks * 16 + ((l >> 3) & 1) * 8;
            ldsm_x2(b0, b1, smem_u32(bp));
            mma16816(acc[n], a0, a1, a2, a3, b0, b1);
        }
    }

    // ---- epilogue: tanh+bias, x att_h, quad reduce -> At ----
    {
        const int grp = l >> 2, qd = l & 3;
        float pA0 = 0.f, pA1 = 0.f, pA2 = 0.f, pA3 = 0.f;
        float pB0 = 0.f, pB1 = 0.f, pB2 = 0.f, pB3 = 0.f;
        #pragma unroll
        for (int n = 0; n < 8; ++n) {
            #pragma unroll
            for (int j = 0; j < 2; ++j) {
                const int col = 8 * n + 2 * qd + j;
                const float bias = Pbs[col];
                float hA = tanh_fast(acc[n][j] + bias);
                float hB = tanh_fast(acc[n][2 + j] + bias);
                float4 av = *reinterpret_cast<const float4*>(Ah + col * 4);
                pA0 += hA * av.x; pA1 += hA * av.y; pA2 += hA * av.z; pA3 += hA * av.w;
                pB0 += hB * av.x; pB1 += hB * av.y; pB2 += hB * av.z; pB3 += hB * av.w;
            }
        }
        #pragma unroll
        for (int off = 1; off <= 2; off <<= 1) {
            pA0 += __shfl_xor_sync(0xffffffffu, pA0, off);
            pA1 += __shfl_xor_sync(0xffffffffu, pA1, off);
            pA2 += __shfl_xor_sync(0xffffffffu, pA2, off);
            pA3 += __shfl_xor_sync(0xffffffffu, pA3, off);
            pB0 += __shfl_xor_sync(0xffffffffu, pB0, off);
            pB1 += __shfl_xor_sync(0xffffffffu, pB1, off);
            pB2 += __shfl_xor_sync(0xffffffffu, pB2, off);
            pB3 += __shfl_xor_sync(0xffffffffu, pB3, off);
        }
        if (qd == 0) {
            const int rA = 16 * w + grp;
            *reinterpret_cast<float4*>(At + rA * 4) =
                make_float4(pA0, pA1, pA2, pA3);
            *reinterpret_cast<float4*>(At + (rA + 8) * 4) =
                make_float4(pB0, pB1, pB2, pB3);
        }
    }
    __syncthreads();                       // At ready

    // ---- ragged softmax: warp j -> bag j ----
    if (w < NB) {
        const int k = l & 3, grp = l >> 2;
        const int c = s_cnt[w];
        float* ab = At + (w * MAXI) * KN + k;
        float m = -1e30f;
        #pragma unroll
        for (int it = 0; it < 8; ++it) {
            int i = grp + (it << 3);
            if (i < c) m = fmaxf(m, ab[i * KN]);
        }
        #pragma unroll
        for (int off = 4; off <= 16; off <<= 1)
            m = fmaxf(m, __shfl_xor_sync(0xffffffffu, m, off));
        float s = 0.f;
        #pragma unroll
        for (int it = 0; it < 8; ++it) {
            int i = grp + (it << 3);
            if (i < c) {
                float e = __expf(ab[i * KN] - m);
                ab[i * KN] = e;
                s += e;
            }
        }
        #pragma unroll
        for (int off = 4; off <= 16; off <<= 1)
            s += __shfl_xor_sync(0xffffffffu, s, off);
        if (grp == 0) red[w * KN + k] = (s > 0.f) ? 1.0f / s : 0.f;
    }
    __syncthreads();                       // weights + red ready

    // ---- pooling: 128 threads = 2 bags x 64 d; E fp32 from global ----
    if (tid < 128) {
        const int b = tid >> 6, d = tid & 63;
        const int bg = blockIdx.x * NB + b;
        if (bg < nseg) {
            const int c = s_cnt[b];
            const long long* sx = s_idx + b * MAXI;
            const float* ap = At + (b * MAXI) * KN;
            ull a01 = 0ull, a23 = 0ull;
            #pragma unroll 4
            for (int i = 0; i < c; ++i) {
                float e = __ldg(emb + sx[i] * (long long)Dm + d);
                double2 wv = *reinterpret_cast<const double2*>(ap + i * KN);
                ull eb = bcast2(e);
                ffma2(a01, eb, __double_as_longlong(wv.x));
                ffma2(a23, eb, __double_as_longlong(wv.y));
            }
            float r0, r1, r2, r3;
            unpack2(r0, r1, a01);
            unpack2(r2, r3, a23);
            float* op = out + (size_t)bg * (KN * Dm) + d;
            op[0]      = r0 * red[b * KN + 0];
            op[Dm]     = r1 * red[b * KN + 1];
            op[2 * Dm] = r2 * red[b * KN + 2];
            op[3 * Dm] = r3 * red[b * KN + 3];
        }
    }
}

extern "C" void kernel_launch(void* const* d_in, const int* in_sizes, int n_in,
                              void* d_out, int out_size) {
    const void*  input_  = d_in[0];
    const void*  offsets = d_in[1];
    const float* emb     = (const float*)d_in[2];
    const float* projw   = (const float*)d_in[3];
    const float* projb   = (const float*)d_in[4];
    const float* atth    = (const float*)d_in[5];
    float* out = (float*)d_out;

    const int       nseg  = in_sizes[1];
    const long long nnz   = in_sizes[0];
    const long long vocab = (long long)in_sizes[2] / Dm;

    prep_kernel<<<1, 256>>>(projw, input_, offsets, nnz, nseg, vocab);

    const int grid = (nseg + NB - 1) / NB;
    pooled_att_hmma<<<grid, NT>>>(input_, offsets, emb, projb,
                                  atth, out, nseg, nnz);
}

// round 9
// speedup vs baseline: 1.6483x; 1.0788x over previous
#include <cuda_runtime.h>
#include <cuda_bf16.h>

// Pooled attention embedding bag, GB300 (sm_103) — HMMA tensor-core version.
//   B=8192 bags, L<=64/bag (via offsets), D=64, ATT=64, K=4.
//   out[b,k,:] = sum_i softmax_i( tanh(E_i @ Wp^T + b) @ att_h )[k] * E_i
//
// R9: 4 bags/CTA (M=256 item rows), 8 warps, dynamic smem 53.6KB, 64 regs
//     -> 4 CTAs/SM (50% occ). HMMA in two m-passes per warp (epilogue inside
//     the pass keeps regs at 64). Softmax: 4 warps. Pooling: all 256 threads.
//   GEMM: mma.m16n8k16.row.col.f32.bf16.bf16.f32, ldmatrix from 72-elem rows.
//   projw is used untransposed (it IS the .col B layout); bf16-converted once.

namespace {
constexpr int Dm = 64, KN = 4, NB = 4, MAXI = 64, NT = 256;
constexpr int NROW = NB * MAXI;       // 256
constexpr int LDA  = 72;              // bf16 row stride (144B)
// dynamic smem offsets (bytes)
constexpr int AS_OFF  = 0;                     // bf16 As[256][72]  36864
constexpr int BS_OFF  = 36864;                 // bf16 Bs[64][72]    9216
constexpr int AT_OFF  = 46080;                 // float At[256][4]   4096
constexpr int AH_OFF  = 50176;                 // float Ah[64][4]    1024
constexpr int PB_OFF  = 51200;                 // float Pb[64]        256
constexpr int RED_OFF = 51456;                 // float red[4][4]      64
constexpr int IDX_OFF = 51520;                 // ll s_idx[256]      2048
constexpr int ST_OFF  = 53568;                 // ll s_start[4]        32
constexpr int CNT_OFF = 53600;                 // int s_cnt[4]         16
constexpr int SMEM_BYTES = 53632;
}

__device__ int      g_idx_is64;
__device__ unsigned g_Wb[2048];  // projw as bf16x2, row-major [64][64]

using ull = unsigned long long;

__device__ __forceinline__ float tanh_fast(float x) {
    float y; asm("tanh.approx.f32 %0, %1;" : "=f"(y) : "f"(x)); return y;
}
__device__ __forceinline__ void ffma2(ull& d, ull a, ull b) {
    asm("fma.rn.f32x2 %0, %1, %2, %0;" : "+l"(d) : "l"(a), "l"(b));
}
__device__ __forceinline__ ull bcast2(float x) {
    ull r; asm("mov.b64 %0, {%1, %1};" : "=l"(r) : "f"(x)); return r;
}
__device__ __forceinline__ void unpack2(float& lo, float& hi, ull v) {
    asm("mov.b64 {%0, %1}, %2;" : "=f"(lo), "=f"(hi) : "l"(v));
}
__device__ __forceinline__ long long ld_idx(const void* p, long long i, int is64) {
    return is64 ? ((const long long*)p)[i] : (long long)((const int*)p)[i];
}
__device__ __forceinline__ unsigned smem_u32(const void* p) {
    unsigned a;
    asm("{ .reg .u64 t; cvta.to.shared.u64 t, %1; cvt.u32.u64 %0, t; }"
        : "=r"(a) : "l"(p));
    return a;
}
__device__ __forceinline__ void ldsm_x4(unsigned& r0, unsigned& r1,
                                        unsigned& r2, unsigned& r3, unsigned addr) {
    asm volatile("ldmatrix.sync.aligned.m8n8.x4.shared.b16 {%0,%1,%2,%3}, [%4];"
                 : "=r"(r0), "=r"(r1), "=r"(r2), "=r"(r3) : "r"(addr));
}
__device__ __forceinline__ void ldsm_x2(unsigned& r0, unsigned& r1, unsigned addr) {
    asm volatile("ldmatrix.sync.aligned.m8n8.x2.shared.b16 {%0,%1}, [%2];"
                 : "=r"(r0), "=r"(r1) : "r"(addr));
}
__device__ __forceinline__ void mma16816(float* c, unsigned a0, unsigned a1,
                                         unsigned a2, unsigned a3,
                                         unsigned b0, unsigned b1) {
    asm volatile(
        "mma.sync.aligned.m16n8k16.row.col.f32.bf16.bf16.f32 "
        "{%0,%1,%2,%3}, {%4,%5,%6,%7}, {%8,%9}, {%0,%1,%2,%3};"
        : "+f"(c[0]), "+f"(c[1]), "+f"(c[2]), "+f"(c[3])
        : "r"(a0), "r"(a1), "r"(a2), "r"(a3), "r"(b0), "r"(b1));
}

// prep: projw fp32 -> bf16 (row-major; already the .col B layout); dtype detect.
extern "C" __global__ void prep_kernel(const float* __restrict__ projw,
                                       const void* __restrict__ input_,
                                       const void* __restrict__ offsets,
                                       long long nnz, int nseg, long long vocab) {
    int t = threadIdx.x;
    for (int q = t; q < 2048; q += 256) {
        __nv_bfloat162 v = __floats2bfloat162_rn(projw[2 * q], projw[2 * q + 1]);
        g_Wb[q] = *reinterpret_cast<unsigned*>(&v);
    }
    if (t == 0) {
        bool ok = true;
        const long long* o64 = (const long long*)offsets;
        int no = nseg < 4 ? nseg : 4;
        long long prev = -1;
        for (int i = 0; i < no; ++i) {
            long long v = o64[i];
            if (v < 0 || v > nnz || v < prev) ok = false;
            prev = v;
        }
        const long long* in64 = (const long long*)input_;
        long long ni = nnz < 8 ? nnz : 8;
        for (long long i = 0; i < ni; ++i) {
            long long v = in64[i];
            if (v < 0 || v >= vocab) ok = false;
        }
        g_idx_is64 = ok ? 1 : 0;
    }
}

extern "C" __global__ void __launch_bounds__(NT, 4)
pooled_att_hmma(const void*  __restrict__ input_,
                const void*  __restrict__ offsets,
                const float* __restrict__ emb,
                const float* __restrict__ projb,
                const float* __restrict__ atth,
                float*       __restrict__ out,
                int nseg, long long nnz)
{
    extern __shared__ __align__(16) char smem[];
    __nv_bfloat16* As   = (__nv_bfloat16*)(smem + AS_OFF);
    __nv_bfloat16* Bs   = (__nv_bfloat16*)(smem + BS_OFF);
    float*     At       = (float*)(smem + AT_OFF);
    float*     Ah       = (float*)(smem + AH_OFF);
    float*     Pbs      = (float*)(smem + PB_OFF);
    float*     red      = (float*)(smem + RED_OFF);
    long long* s_idx    = (long long*)(smem + IDX_OFF);
    long long* s_start  = (long long*)(smem + ST_OFF);
    int*       s_cnt    = (int*)(smem + CNT_OFF);

    const int tid = threadIdx.x;
    const int w   = tid >> 5;
    const int l   = tid & 31;
    const int is64 = g_idx_is64;

    if (tid < NB) {
        int bg = blockIdx.x * NB + tid;
        long long st = 0, en = 0;
        if (bg < nseg) {
            st = ld_idx(offsets, bg, is64);
            en = (bg + 1 < nseg) ? ld_idx(offsets, bg + 1, is64) : nnz;
        }
        long long c = en - st;
        if (c < 0) c = 0;
        if (c > MAXI) c = MAXI;
        s_cnt[tid] = (int)c;
        s_start[tid] = st;
    }
    // stage B (bf16, padded rows), Ah, Pb
    for (int q = tid; q < 2048; q += NT) {
        int row = q >> 5, cp = q & 31;
        *reinterpret_cast<unsigned*>(Bs + row * LDA + cp * 2) = g_Wb[q];
    }
    if (tid < 64) Pbs[tid] = projb[tid];
    if (tid < 256) Ah[tid] = atth[tid];
    __syncthreads();                       // s_cnt ready

    // ---- gather: 2 threads per item row, 2 row-waves; fp32 -> bf16 ----
    {
        const int half = tid & 1;
        for (int row = tid >> 1; row < NROW; row += NT / 2) {
            const int b = row >> 6, it = row & 63;
            const bool valid = it < s_cnt[b];
            long long idx = 0;
            if (valid) idx = ld_idx(input_, s_start[b] + it, is64);
            if (half == 0) s_idx[row] = idx;
            const float4* src =
                reinterpret_cast<const float4*>(emb + idx * (long long)Dm + half * 32);
            __nv_bfloat16* dst = As + row * LDA + half * 32;
            #pragma unroll
            for (int c = 0; c < 8; ++c) {
                float4 v = make_float4(0.f, 0.f, 0.f, 0.f);
                if (valid) v = src[c];
                __nv_bfloat162 lo = __floats2bfloat162_rn(v.x, v.y);
                __nv_bfloat162 hi = __floats2bfloat162_rn(v.z, v.w);
                ull pv = ((ull)(*reinterpret_cast<unsigned*>(&hi)) << 32)
                       |  (ull)(*reinterpret_cast<unsigned*>(&lo));
                *reinterpret_cast<ull*>(dst + c * 4) = pv;
            }
        }
    }
    __syncthreads();                       // As + Bs ready

    // ---- HMMA GEMM in 2 m-passes; epilogue inside pass (regs stay low) ----
    for (int pass = 0; pass < 2; ++pass) {
        const int rbase = pass * 128 + 16 * w;

        float acc[8][4];
        #pragma unroll
        for (int n = 0; n < 8; ++n)
            #pragma unroll
            for (int j = 0; j < 4; ++j) acc[n][j] = 0.f;

        #pragma unroll
        for (int ks = 0; ks < 4; ++ks) {
            unsigned a0, a1, a2, a3;
            {
                const __nv_bfloat16* ap =
                    As + (rbase + (l & 15)) * LDA + ks * 16 + (l >> 4) * 8;
                ldsm_x4(a0, a1, a2, a3, smem_u32(ap));
            }
            #pragma unroll
            for (int n = 0; n < 8; ++n) {
                unsigned b0, b1;
                const __nv_bfloat16* bp =
                    Bs + (8 * n + (l & 7)) * LDA + ks * 16 + ((l >> 3) & 1) * 8;
                ldsm_x2(b0, b1, smem_u32(bp));
                mma16816(acc[n], a0, a1, a2, a3, b0, b1);
            }
        }

        // epilogue: tanh+bias, x att_h, quad reduce -> At
        {
            const int grp = l >> 2, qd = l & 3;
            float pA0 = 0.f, pA1 = 0.f, pA2 = 0.f, pA3 = 0.f;
            float pB0 = 0.f, pB1 = 0.f, pB2 = 0.f, pB3 = 0.f;
            #pragma unroll
            for (int n = 0; n < 8; ++n) {
                #pragma unroll
                for (int j = 0; j < 2; ++j) {
                    const int col = 8 * n + 2 * qd + j;
                    const float bias = Pbs[col];
                    float hA = tanh_fast(acc[n][j] + bias);
                    float hB = tanh_fast(acc[n][2 + j] + bias);
                    float4 av = *reinterpret_cast<const float4*>(Ah + col * 4);
                    pA0 += hA * av.x; pA1 += hA * av.y; pA2 += hA * av.z; pA3 += hA * av.w;
                    pB0 += hB * av.x; pB1 += hB * av.y; pB2 += hB * av.z; pB3 += hB * av.w;
                }
            }
            #pragma unroll
            for (int off = 1; off <= 2; off <<= 1) {
                pA0 += __shfl_xor_sync(0xffffffffu, pA0, off);
                pA1 += __shfl_xor_sync(0xffffffffu, pA1, off);
                pA2 += __shfl_xor_sync(0xffffffffu, pA2, off);
                pA3 += __shfl_xor_sync(0xffffffffu, pA3, off);
                pB0 += __shfl_xor_sync(0xffffffffu, pB0, off);
                pB1 += __shfl_xor_sync(0xffffffffu, pB1, off);
                pB2 += __shfl_xor_sync(0xffffffffu, pB2, off);
                pB3 += __shfl_xor_sync(0xffffffffu, pB3, off);
            }
            if (qd == 0) {
                const int rA = rbase + grp;
                *reinterpret_cast<float4*>(At + rA * 4) =
                    make_float4(pA0, pA1, pA2, pA3);
                *reinterpret_cast<float4*>(At + (rA + 8) * 4) =
                    make_float4(pB0, pB1, pB2, pB3);
            }
        }
    }
    __syncthreads();                       // At ready

    // ---- ragged softmax: warp j -> bag j (4 warps active) ----
    if (w < NB) {
        const int k = l & 3, grp = l >> 2;
        const int c = s_cnt[w];
        float* ab = At + (w * MAXI) * KN + k;
        float m = -1e30f;
        #pragma unroll
        for (int it = 0; it < 8; ++it) {
            int i = grp + (it << 3);
            if (i < c) m = fmaxf(m, ab[i * KN]);
        }
        #pragma unroll
        for (int off = 4; off <= 16; off <<= 1)
            m = fmaxf(m, __shfl_xor_sync(0xffffffffu, m, off));
        float s = 0.f;
        #pragma unroll
        for (int it = 0; it < 8; ++it) {
            int i = grp + (it << 3);
            if (i < c) {
                float e = __expf(ab[i * KN] - m);
                ab[i * KN] = e;
                s += e;
            }
        }
        #pragma unroll
        for (int off = 4; off <= 16; off <<= 1)
            s += __shfl_xor_sync(0xffffffffu, s, off);
        if (grp == 0) red[w * KN + k] = (s > 0.f) ? 1.0f / s : 0.f;
    }
    __syncthreads();                       // weights + red ready

    // ---- pooling: all 256 threads = 4 bags x 64 d; E fp32 from global ----
    {
        const int b = tid >> 6, d = tid & 63;
        const int bg = blockIdx.x * NB + b;
        if (bg < nseg) {
            const int c = s_cnt[b];
            const long long* sx = s_idx + b * MAXI;
            const float* ap = At + (b * MAXI) * KN;
            ull a01 = 0ull, a23 = 0ull;
            int i = 0;
            for (; i + 4 <= c; i += 4) {
                long long i0 = sx[i], i1 = sx[i+1], i2 = sx[i+2], i3 = sx[i+3];
                float e0 = __ldg(emb + i0 * (long long)Dm + d);
                float e1 = __ldg(emb + i1 * (long long)Dm + d);
                float e2 = __ldg(emb + i2 * (long long)Dm + d);
                float e3 = __ldg(emb + i3 * (long long)Dm + d);
                double2 w0 = *reinterpret_cast<const double2*>(ap + (i + 0) * KN);
                double2 w1 = *reinterpret_cast<const double2*>(ap + (i + 1) * KN);
                double2 w2 = *reinterpret_cast<const double2*>(ap + (i + 2) * KN);
                double2 w3 = *reinterpret_cast<const double2*>(ap + (i + 3) * KN);
                ffma2(a01, bcast2(e0), __double_as_longlong(w0.x));
                ffma2(a23, bcast2(e0), __double_as_longlong(w0.y));
                ffma2(a01, bcast2(e1), __double_as_longlong(w1.x));
                ffma2(a23, bcast2(e1), __double_as_longlong(w1.y));
                ffma2(a01, bcast2(e2), __double_as_longlong(w2.x));
                ffma2(a23, bcast2(e2), __double_as_longlong(w2.y));
                ffma2(a01, bcast2(e3), __double_as_longlong(w3.x));
                ffma2(a23, bcast2(e3), __double_as_longlong(w3.y));
            }
            for (; i < c; ++i) {
                float e = __ldg(emb + sx[i] * (long long)Dm + d);
                double2 wv = *reinterpret_cast<const double2*>(ap + i * KN);
                ffma2(a01, bcast2(e), __double_as_longlong(wv.x));
                ffma2(a23, bcast2(e), __double_as_longlong(wv.y));
            }
            float r0, r1, r2, r3;
            unpack2(r0, r1, a01);
            unpack2(r2, r3, a23);
            float* op = out + (size_t)bg * (KN * Dm) + d;
            op[0]      = r0 * red[b * KN + 0];
            op[Dm]     = r1 * red[b * KN + 1];
            op[2 * Dm] = r2 * red[b * KN + 2];
            op[3 * Dm] = r3 * red[b * KN + 3];
        }
    }
}

extern "C" void kernel_launch(void* const* d_in, const int* in_sizes, int n_in,
                              void* d_out, int out_size) {
    const void*  input_  = d_in[0];
    const void*  offsets = d_in[1];
    const float* emb     = (const float*)d_in[2];
    const float* projw   = (const float*)d_in[3];
    const float* projb   = (const float*)d_in[4];
    const float* atth    = (const float*)d_in[5];
    float* out = (float*)d_out;

    const int       nseg  = in_sizes[1];
    const long long nnz   = in_sizes[0];
    const long long vocab = (long long)in_sizes[2] / Dm;

    prep_kernel<<<1, 256>>>(projw, input_, offsets, nnz, nseg, vocab);

    cudaFuncSetAttribute(pooled_att_hmma,
                         cudaFuncAttributeMaxDynamicSharedMemorySize, SMEM_BYTES);
    const int grid = (nseg + NB - 1) / NB;
    pooled_att_hmma<<<grid, NT, SMEM_BYTES>>>(input_, offsets, emb, projb,
                                              atth, out, nseg, nnz);
}